// round 5
// baseline (speedup 1.0000x reference)
#include <cuda_runtime.h>
#include <cstdint>

#define NUM_EXPERTS 8
#define HIDDEN 1024
#define INTER 4096
#define NTOK 2048
#define SOFTCAPV 30.0f
#define MAXROWS (NTOK * 2)

// tcgen05 only exists under arch-specific ('a') compilation. The harness's
// virtual arch may be compute_103 (no 'a'); guard so every pass compiles.
#if defined(__CUDA_ARCH__) && (defined(__CUDA_ARCH_FEAT_SM103_ALL) || \
    defined(__CUDA_ARCH_FEAT_SM100_ALL) || defined(__CUDA_ARCH_SPECIFIC__) || \
    defined(__CUDA_ARCH_FAMILY_SPECIFIC__))
#define USE_TCGEN05 1
#else
#define USE_TCGEN05 0
#endif

// ---------------- scratch (device globals; no allocs allowed) ----------------
__device__ int   g_counts[NUM_EXPERTS];
__device__ int   g_base[NUM_EXPERTS];
__device__ int   g_fill[NUM_EXPERTS];
__device__ int   g_row_token[MAXROWS];
__device__ float g_row_weight[MAXROWS];
__device__ int   g_tok_e[NTOK * 2];
__device__ float g_tok_w[NTOK * 2];
__device__ float g_scratch[(size_t)MAXROWS * INTER];   // 64 MB act buffer

// ---------------- generic PTX helpers (legal on sm_103 base) ----------------
__device__ __forceinline__ uint32_t elect_one() {
    uint32_t pred;
    asm volatile("{\n\t.reg .pred p;\n\telect.sync _|p, 0xFFFFFFFF;\n\t"
                 "selp.b32 %0, 1, 0, p;\n\t}" : "=r"(pred));
    return pred;
}
__device__ __forceinline__ uint32_t smem_u32(const void* p) {
    uint32_t a;
    asm("{ .reg .u64 t; cvta.to.shared.u64 t, %1; cvt.u32.u64 %0, t; }"
        : "=r"(a) : "l"(p));
    return a;
}

#define MBARRIER_INIT(addr, cnt) \
    asm volatile("mbarrier.init.shared.b64 [%0], %1;" :: "r"(addr), "r"(cnt) : "memory")

#define MBARRIER_WAIT_PARITY(addr, par) do {                                   \
    uint32_t _m = (addr); uint32_t _p = (par); uint32_t _d;                    \
    asm volatile("{\n\t.reg .pred p;\n\t"                                      \
        "mbarrier.try_wait.parity.acquire.cta.shared::cta.b64 p, [%1], %2;\n\t"\
        "selp.b32 %0, 1, 0, p;\n\t}" : "=r"(_d) : "r"(_m), "r"(_p) : "memory");\
    if (!_d) {                                                                 \
        asm volatile("{\n\t.reg .pred P1;\n\t"                                 \
            "WL_%=:\n\t"                                                       \
            "mbarrier.try_wait.parity.acquire.cta.shared::cta.b64 P1, [%0], %1, 0x989680;\n\t" \
            "@P1 bra.uni WD_%=;\n\t bra.uni WL_%=;\n\t WD_%=:\n\t}"            \
            :: "r"(_m), "r"(_p) : "memory");                                   \
    } } while (0)

__device__ __forceinline__ void cp_async16(uint32_t dst, const void* src, int src_sz) {
    asm volatile("cp.async.cg.shared.global [%0], [%1], 16, %2;\n"
                 :: "r"(dst), "l"(src), "r"(src_sz));
}
__device__ __forceinline__ uint32_t f2tf32(float f) {
    uint32_t u;
    asm("cvt.rna.tf32.f32 %0, %1;" : "=r"(u) : "f"(f));
    return u;
}
__device__ __forceinline__ void mma_tf32_sync(float* c, const uint32_t* a, const uint32_t* b) {
    asm volatile(
        "mma.sync.aligned.m16n8k8.row.col.f32.tf32.tf32.f32 "
        "{%0,%1,%2,%3},{%4,%5,%6,%7},{%8,%9},{%0,%1,%2,%3};"
        : "+f"(c[0]), "+f"(c[1]), "+f"(c[2]), "+f"(c[3])
        : "r"(a[0]), "r"(a[1]), "r"(a[2]), "r"(a[3]), "r"(b[0]), "r"(b[1]));
}

// ---------------- tcgen05 helpers (only instantiated under USE_TCGEN05) ------
#define TCGEN05_ALLOC(saddr, ncols) \
    asm volatile("tcgen05.alloc.cta_group::1.sync.aligned.shared::cta.b32 [%0], %1;" \
                 :: "r"(saddr), "r"(ncols) : "memory")
#define TCGEN05_RELINQ() \
    asm volatile("tcgen05.relinquish_alloc_permit.cta_group::1.sync.aligned;")
#define TCGEN05_DEALLOC(tm, ncols) \
    asm volatile("tcgen05.dealloc.cta_group::1.sync.aligned.b32 %0, %1;" :: "r"(tm), "r"(ncols))
#define TCGEN05_COMMIT(maddr) \
    asm volatile("tcgen05.commit.cta_group::1.mbarrier::arrive::one.shared::cluster.b64 [%0];" \
                 :: "r"(maddr) : "memory")
#define TCGEN05_FENCE_AFTER() \
    asm volatile("tcgen05.fence::after_thread_sync;" ::: "memory")
#define TCGEN05_FENCE_BEFORE() \
    asm volatile("tcgen05.fence::before_thread_sync;" ::: "memory")
#define TCGEN05_WAIT_LD() \
    asm volatile("tcgen05.wait::ld.sync.aligned;" ::: "memory")

#define TCGEN05_LD_X32(r, tm) \
    asm volatile("tcgen05.ld.sync.aligned.32x32b.x32.b32 " \
        "{%0, %1, %2, %3, %4, %5, %6, %7, %8, %9, %10, %11, %12, %13, %14, %15, " \
        " %16, %17, %18, %19, %20, %21, %22, %23, %24, %25, %26, %27, %28, %29, %30, %31}, [%32];" \
        : "=r"((r)[0]),  "=r"((r)[1]),  "=r"((r)[2]),  "=r"((r)[3]),  \
          "=r"((r)[4]),  "=r"((r)[5]),  "=r"((r)[6]),  "=r"((r)[7]),  \
          "=r"((r)[8]),  "=r"((r)[9]),  "=r"((r)[10]), "=r"((r)[11]), \
          "=r"((r)[12]), "=r"((r)[13]), "=r"((r)[14]), "=r"((r)[15]), \
          "=r"((r)[16]), "=r"((r)[17]), "=r"((r)[18]), "=r"((r)[19]), \
          "=r"((r)[20]), "=r"((r)[21]), "=r"((r)[22]), "=r"((r)[23]), \
          "=r"((r)[24]), "=r"((r)[25]), "=r"((r)[26]), "=r"((r)[27]), \
          "=r"((r)[28]), "=r"((r)[29]), "=r"((r)[30]), "=r"((r)[31]) \
        : "r"(tm))

__device__ __forceinline__ uint64_t make_desc_sw128(uint32_t addr) {
    const uint64_t base = (uint64_t(2) << 61) | (uint64_t(1) << 46) |
                          (uint64_t(64) << 32) | (uint64_t(1) << 16);
    return base | ((uint64_t)(addr >> 4) & 0x3FFF);
}

#if USE_TCGEN05
__device__ __forceinline__ void mma_tf32_ss(uint32_t d, uint64_t a, uint64_t b,
                                            uint32_t idesc, uint32_t en) {
    asm volatile("{\n\t.reg .pred p;\n\tsetp.ne.u32 p, %4, 0;\n\t"
        "tcgen05.mma.cta_group::1.kind::tf32 [%0], %1, %2, %3, {%5,%5,%5,%5}, p;\n\t}"
        :: "r"(d), "l"(a), "l"(b), "r"(idesc), "r"(en), "r"(0u) : "memory");
}
#endif

// ---------------- small kernels ----------------
__global__ void k_zero_out(float* __restrict__ out) {
    int i = blockIdx.x * blockDim.x + threadIdx.x;
    ((float4*)out)[i] = make_float4(0.f, 0.f, 0.f, 0.f);
    if (blockIdx.x == 0 && threadIdx.x < NUM_EXPERTS) g_counts[threadIdx.x] = 0;
}

__global__ void k_router(const float* __restrict__ x, const float* __restrict__ wg) {
    int warp = (blockIdx.x * blockDim.x + threadIdx.x) >> 5;
    int lane = threadIdx.x & 31;
    if (warp >= NTOK) return;
    const float* xr = x + (size_t)warp * HIDDEN;
    float acc[NUM_EXPERTS];
#pragma unroll
    for (int e = 0; e < NUM_EXPERTS; e++) acc[e] = 0.f;
    for (int h = lane; h < HIDDEN; h += 32) {
        float xv = xr[h];
#pragma unroll
        for (int e = 0; e < NUM_EXPERTS; e++) acc[e] += xv * wg[e * HIDDEN + h];
    }
#pragma unroll
    for (int off = 16; off; off >>= 1)
#pragma unroll
        for (int e = 0; e < NUM_EXPERTS; e++)
            acc[e] += __shfl_xor_sync(0xffffffffu, acc[e], off);
    if (lane == 0) {
        float l[NUM_EXPERTS];
#pragma unroll
        for (int e = 0; e < NUM_EXPERTS; e++)
            l[e] = SOFTCAPV * tanhf(acc[e] / SOFTCAPV);
        int b = 0; float vb = l[0];
#pragma unroll
        for (int e = 1; e < NUM_EXPERTS; e++) if (l[e] > vb) { b = e; vb = l[e]; }
        int s = -1; float vs = -1e30f;
#pragma unroll
        for (int e = 0; e < NUM_EXPERTS; e++)
            if (e != b && l[e] > vs) { s = e; vs = l[e]; }
        float wa = 1.f / (1.f + expf(vs - vb));
        g_tok_e[2 * warp]     = b;  g_tok_w[2 * warp]     = wa;
        g_tok_e[2 * warp + 1] = s;  g_tok_w[2 * warp + 1] = 1.f - wa;
        atomicAdd(&g_counts[b], 1);
        atomicAdd(&g_counts[s], 1);
    }
}

__global__ void k_offsets() {
    if (threadIdx.x == 0) {
        int acc = 0;
        for (int e = 0; e < NUM_EXPERTS; e++) { g_base[e] = acc; acc += g_counts[e]; }
    }
    if (threadIdx.x < NUM_EXPERTS) g_fill[threadIdx.x] = 0;
}

__global__ void k_scatter() {
    int t = blockIdx.x * blockDim.x + threadIdx.x;
    if (t >= NTOK) return;
#pragma unroll
    for (int k = 0; k < 2; k++) {
        int e = g_tok_e[2 * t + k];
        int p = atomicAdd(&g_fill[e], 1);
        int r = g_base[e] + p;
        g_row_token[r]  = t;
        g_row_weight[r] = g_tok_w[2 * t + k];
    }
}

// ---------------- grouped GEMM ----------------
#define BM 128
#define BN 256
// tcgen05 path staging
#define KSTAGE 32
#define STAGE_A (BM * 128)              // 16 KB
#define STAGE_B (BN * 128)              // 32 KB
#define STAGE_BYTES (STAGE_A + STAGE_B) // 48 KB
#define SMEM_DYN (2 * STAGE_BYTES + 1024)
// fallback staging (fits inside SMEM_DYN)
#define FBK 16
#define FBKP 20
#define F_A_BYTES (BM * FBKP * 4)       // 10240
#define F_B_BYTES (BN * FBKP * 4)       // 20480
#define F_STAGE (F_A_BYTES + F_B_BYTES) // 30720

// idesc: dtype=F32(1)<<4 | atype=TF32(2)<<7 | btype=TF32(2)<<10 | (N/8)<<17 | (M/16)<<24
#define IDESC_TF32 ((1u << 4) | (2u << 7) | (2u << 10) | ((BN / 8) << 17) | ((BM / 16) << 24))

// MODE 0: h1 = gather(x) @ w1^T -> scratch
// MODE 1: h3 = gather(x) @ w3^T ; scratch = gelu(scratch) * h3
// MODE 2: C  = scratch @ w2^T ; out[token] += weight * C (atomic)
template <int MODE, int KDIM, int NDIM>
__global__ void __launch_bounds__(256) k_gemm(const float* __restrict__ Asrc,
                                              const float* __restrict__ W,
                                              float* __restrict__ Out) {
    int e   = blockIdx.z;
    int cnt = g_counts[e];
    int m0  = blockIdx.y * BM;
    if (m0 >= cnt) return;
    int n0    = blockIdx.x * BN;
    int rbase = g_base[e];
    const float* Ap = (MODE == 2) ? (const float*)g_scratch : Asrc;
    const float* B  = W + (size_t)e * NDIM * KDIM;

    extern __shared__ char dynsmem[];
    int tid = threadIdx.x;

#if USE_TCGEN05
    // ================= tcgen05 tf32 SS path =================
    __shared__ uint32_t s_tmem;
    __shared__ __align__(8) uint64_t s_mbar[2];

    uint32_t draw  = smem_u32(dynsmem);
    uint32_t sbase = (draw + 1023u) & ~1023u;
    char*    gbase = dynsmem + (sbase - draw);
    uint32_t mb    = smem_u32(&s_mbar[0]);
    int wid = tid >> 5;

    const float* aptr[4]; int asz[4]; uint32_t aoff[4];
#pragma unroll
    for (int p = 0; p < 4; p++) {
        int idx = tid + p * 256;
        int row = idx >> 3, ch = idx & 7;
        int mg  = m0 + row;
        if (MODE == 2) {
            int r = rbase + (mg < cnt ? mg : 0);
            aptr[p] = Ap + (size_t)r * KDIM + ch * 4;
        } else {
            int t = (mg < cnt) ? g_row_token[rbase + mg] : 0;
            aptr[p] = Ap + (size_t)t * KDIM + ch * 4;
        }
        asz[p] = (mg < cnt) ? 16 : 0;
        uint32_t bo = row * 128 + ch * 16;
        aoff[p] = bo ^ ((bo >> 3) & 0x70);
    }
    const float* bptr[8]; uint32_t boff[8];
#pragma unroll
    for (int p = 0; p < 8; p++) {
        int idx = tid + p * 256;
        int row = idx >> 3, ch = idx & 7;
        bptr[p] = B + (size_t)(n0 + row) * KDIM + ch * 4;
        uint32_t bo = row * 128 + ch * 16;
        boff[p] = bo ^ ((bo >> 3) & 0x70);
    }

    auto issue = [&](int st, int kt) {
        uint32_t sA = sbase + st * STAGE_BYTES;
        uint32_t sB = sA + STAGE_A;
        int k0 = kt * KSTAGE;
#pragma unroll
        for (int p = 0; p < 4; p++) cp_async16(sA + aoff[p], aptr[p] + k0, asz[p]);
#pragma unroll
        for (int p = 0; p < 8; p++) cp_async16(sB + boff[p], bptr[p] + k0, 16);
        asm volatile("cp.async.commit_group;\n");
    };

    auto convert = [&](int st) {
        char* gA = gbase + st * STAGE_BYTES;
        char* gB = gA + STAGE_A;
#pragma unroll
        for (int p = 0; p < 4; p++) {
            float4* q = (float4*)(gA + aoff[p]);
            float4 v = *q;
            *(uint4*)q = make_uint4(f2tf32(v.x), f2tf32(v.y), f2tf32(v.z), f2tf32(v.w));
        }
#pragma unroll
        for (int p = 0; p < 8; p++) {
            float4* q = (float4*)(gB + boff[p]);
            float4 v = *q;
            *(uint4*)q = make_uint4(f2tf32(v.x), f2tf32(v.y), f2tf32(v.z), f2tf32(v.w));
        }
    };

    issue(0, 0);

    if (wid == 0) {
        TCGEN05_ALLOC(smem_u32(&s_tmem), 256);
        TCGEN05_RELINQ();
        if (elect_one()) { MBARRIER_INIT(mb, 1); MBARRIER_INIT(mb + 8, 1); }
    }
    __syncthreads();
    uint32_t tmem = s_tmem;

    uint64_t adesc[2], bdesc[2];
#pragma unroll
    for (int s = 0; s < 2; s++) {
        adesc[s] = make_desc_sw128(sbase + s * STAGE_BYTES);
        bdesc[s] = make_desc_sw128(sbase + s * STAGE_BYTES + STAGE_A);
    }

    constexpr int KT = KDIM / KSTAGE;
    for (int kt = 0; kt < KT; kt++) {
        int s  = kt & 1;
        int lk = kt + 1;
        if (lk < KT) {
            if (lk >= 2) {
                int ph = ((lk - 2) >> 1) & 1;
                MBARRIER_WAIT_PARITY(mb + (lk & 1) * 8, ph);
            }
            issue(lk & 1, lk);
            asm volatile("cp.async.wait_group 1;\n" ::: "memory");
        } else {
            asm volatile("cp.async.wait_group 0;\n" ::: "memory");
        }
        convert(s);
        asm volatile("fence.proxy.async.shared::cta;" ::: "memory");
        __syncthreads();
        if (wid == 0 && elect_one()) {
#pragma unroll
            for (int stp = 0; stp < 4; stp++)
                mma_tf32_ss(tmem, adesc[s] + stp * 2, bdesc[s] + stp * 2,
                            IDESC_TF32, (kt > 0 || stp > 0) ? 1u : 0u);
            TCGEN05_COMMIT(mb + s * 8);
        }
    }

    {
        int fs = (KT - 1) & 1;
        int ph = ((KT / 2) - 1) & 1;
        MBARRIER_WAIT_PARITY(mb + fs * 8, ph);
    }
    TCGEN05_FENCE_AFTER();

    if (tid < 128) {
        int mg = m0 + tid;            // D row = wid*32 + lane = tid (own subpartition)
        bool valid = mg < cnt;
        int t = 0; float wgt = 0.f;
        if (MODE == 2 && valid) { t = g_row_token[rbase + mg]; wgt = g_row_weight[rbase + mg]; }
#pragma unroll
        for (int c0 = 0; c0 < BN; c0 += 32) {
            uint32_t d[32];
            TCGEN05_LD_X32(d, tmem + c0);
            TCGEN05_WAIT_LD();
            if (!valid) continue;
            if (MODE == 0) {
                float* dst = g_scratch + (size_t)(rbase + mg) * INTER + n0 + c0;
#pragma unroll
                for (int j = 0; j < 32; j += 4)
                    *(float4*)(dst + j) = make_float4(
                        __uint_as_float(d[j]), __uint_as_float(d[j + 1]),
                        __uint_as_float(d[j + 2]), __uint_as_float(d[j + 3]));
            } else if (MODE == 1) {
                float* pp = g_scratch + (size_t)(rbase + mg) * INTER + n0 + c0;
#pragma unroll
                for (int j = 0; j < 32; j += 4) {
                    float4 h1 = *(float4*)(pp + j);
                    float4 o;
                    o.x = 0.5f * h1.x * (1.f + erff(h1.x * 0.70710678118654752f)) * __uint_as_float(d[j]);
                    o.y = 0.5f * h1.y * (1.f + erff(h1.y * 0.70710678118654752f)) * __uint_as_float(d[j + 1]);
                    o.z = 0.5f * h1.z * (1.f + erff(h1.z * 0.70710678118654752f)) * __uint_as_float(d[j + 2]);
                    o.w = 0.5f * h1.w * (1.f + erff(h1.w * 0.70710678118654752f)) * __uint_as_float(d[j + 3]);
                    *(float4*)(pp + j) = o;
                }
            } else {
                float* op = Out + (size_t)t * HIDDEN + n0 + c0;
#pragma unroll
                for (int j = 0; j < 32; j++)
                    atomicAdd(op + j, wgt * __uint_as_float(d[j]));
            }
        }
        TCGEN05_FENCE_BEFORE();
    }

    __syncthreads();
    if (wid == 0) TCGEN05_DEALLOC(tmem, 256);

#else
    // ================= fallback: mma.sync tf32 (sm_103 base ISA) =============
    // SMEM: stage st at dynsmem + st*F_STAGE; A rows [BM][FBKP] f32, B [BN][FBKP].
    int lane = tid & 31, warp = tid >> 5;
    int wm = warp & 1, wn = warp >> 1;       // 2 x 4 warps, warp tile 64 x 64
    int g = lane >> 2, tg = lane & 3;

    auto As = [&](int st, int r, int c) -> float* {
        return (float*)(dynsmem + st * F_STAGE) + r * FBKP + c;
    };
    auto Bs = [&](int st, int r, int c) -> float* {
        return (float*)(dynsmem + st * F_STAGE + F_A_BYTES) + r * FBKP + c;
    };

    const float* aptr[2]; int asz[2];
#pragma unroll
    for (int p = 0; p < 2; p++) {
        int idx = tid + p * 256;
        int row = idx >> 2, ch = idx & 3;
        int mg = m0 + row;
        if (MODE == 2) {
            int r = rbase + (mg < cnt ? mg : 0);
            aptr[p] = Ap + (size_t)r * KDIM + ch * 4;
        } else {
            int t = (mg < cnt) ? g_row_token[rbase + mg] : 0;
            aptr[p] = Ap + (size_t)t * KDIM + ch * 4;
        }
        asz[p] = (mg < cnt) ? 16 : 0;
    }
    const float* bptr[4];
#pragma unroll
    for (int p = 0; p < 4; p++) {
        int idx = tid + p * 256;
        int row = idx >> 2, ch = idx & 3;
        bptr[p] = B + (size_t)(n0 + row) * KDIM + ch * 4;
    }

    float acc[4][8][4];
#pragma unroll
    for (int i = 0; i < 4; i++)
#pragma unroll
        for (int j = 0; j < 8; j++)
#pragma unroll
            for (int c = 0; c < 4; c++) acc[i][j][c] = 0.f;

    auto issueF = [&](int st, int kt) {
        int k0 = kt * FBK;
#pragma unroll
        for (int p = 0; p < 2; p++) {
            int idx = tid + p * 256;
            int row = idx >> 2, ch = idx & 3;
            cp_async16(smem_u32(As(st, row, ch * 4)), aptr[p] + k0, asz[p]);
        }
#pragma unroll
        for (int p = 0; p < 4; p++) {
            int idx = tid + p * 256;
            int row = idx >> 2, ch = idx & 3;
            cp_async16(smem_u32(Bs(st, row, ch * 4)), bptr[p] + k0, 16);
        }
        asm volatile("cp.async.commit_group;\n");
    };

    auto convertF = [&](int st) {   // round own chunks fp32 -> tf32(RNA) in place
#pragma unroll
        for (int p = 0; p < 2; p++) {
            int idx = tid + p * 256;
            float4* q = (float4*)As(st, idx >> 2, (idx & 3) * 4);
            float4 v = *q;
            *(uint4*)q = make_uint4(f2tf32(v.x), f2tf32(v.y), f2tf32(v.z), f2tf32(v.w));
        }
#pragma unroll
        for (int p = 0; p < 4; p++) {
            int idx = tid + p * 256;
            float4* q = (float4*)Bs(st, idx >> 2, (idx & 3) * 4);
            float4 v = *q;
            *(uint4*)q = make_uint4(f2tf32(v.x), f2tf32(v.y), f2tf32(v.z), f2tf32(v.w));
        }
    };

    constexpr int KT = KDIM / FBK;
    issueF(0, 0);
    for (int kt = 0; kt < KT; ++kt) {
        int cur = kt & 1;
        if (kt + 1 < KT) {
            issueF(cur ^ 1, kt + 1);
            asm volatile("cp.async.wait_group 1;\n" ::: "memory");
        } else {
            asm volatile("cp.async.wait_group 0;\n" ::: "memory");
        }
        convertF(cur);
        __syncthreads();
#pragma unroll
        for (int kk = 0; kk < FBK; kk += 8) {
            uint32_t a[4][4], b[8][2];
#pragma unroll
            for (int mt = 0; mt < 4; mt++) {
                int r = wm * 64 + mt * 16;
                a[mt][0] = __float_as_uint(*As(cur, r + g,     kk + tg));
                a[mt][1] = __float_as_uint(*As(cur, r + g + 8, kk + tg));
                a[mt][2] = __float_as_uint(*As(cur, r + g,     kk + tg + 4));
                a[mt][3] = __float_as_uint(*As(cur, r + g + 8, kk + tg + 4));
            }
#pragma unroll
            for (int nt = 0; nt < 8; nt++) {
                int c = wn * 64 + nt * 8;
                b[nt][0] = __float_as_uint(*Bs(cur, c + g, kk + tg));
                b[nt][1] = __float_as_uint(*Bs(cur, c + g, kk + tg + 4));
            }
#pragma unroll
            for (int mt = 0; mt < 4; mt++)
#pragma unroll
                for (int nt = 0; nt < 8; nt++)
                    mma_tf32_sync(acc[mt][nt], a[mt], b[nt]);
        }
        __syncthreads();
    }

#pragma unroll
    for (int mt = 0; mt < 4; mt++) {
#pragma unroll
        for (int nt = 0; nt < 8; nt++) {
#pragma unroll
            for (int cr = 0; cr < 4; cr++) {
                int row = wm * 64 + mt * 16 + g + ((cr >> 1) ? 8 : 0);
                int mg = m0 + row;
                if (mg >= cnt) continue;
                int col = n0 + wn * 64 + nt * 8 + tg * 2 + (cr & 1);
                float v = acc[mt][nt][cr];
                if (MODE == 0) {
                    g_scratch[(size_t)(rbase + mg) * INTER + col] = v;
                } else if (MODE == 1) {
                    size_t idx = (size_t)(rbase + mg) * INTER + col;
                    float h1 = g_scratch[idx];
                    float ge = 0.5f * h1 * (1.f + erff(h1 * 0.70710678118654752f));
                    g_scratch[idx] = ge * v;
                } else {
                    int t  = g_row_token[rbase + mg];
                    float w = g_row_weight[rbase + mg];
                    atomicAdd(&Out[(size_t)t * HIDDEN + col], w * v);
                }
            }
        }
    }
#endif
}

// ---------------- launch ----------------
extern "C" void kernel_launch(void* const* d_in, const int* in_sizes, int n_in,
                              void* d_out, int out_size) {
    const float* x  = (const float*)d_in[0];
    const float* wg = (const float*)d_in[1];
    const float* w1 = (const float*)d_in[2];
    const float* w3 = (const float*)d_in[3];
    const float* w2 = (const float*)d_in[4];
    float* out = (float*)d_out;

    cudaFuncSetAttribute(k_gemm<0, HIDDEN, INTER>,
                         cudaFuncAttributeMaxDynamicSharedMemorySize, SMEM_DYN);
    cudaFuncSetAttribute(k_gemm<1, HIDDEN, INTER>,
                         cudaFuncAttributeMaxDynamicSharedMemorySize, SMEM_DYN);
    cudaFuncSetAttribute(k_gemm<2, INTER, HIDDEN>,
                         cudaFuncAttributeMaxDynamicSharedMemorySize, SMEM_DYN);

    k_zero_out<<<2048, 256>>>(out);
    k_router<<<256, 256>>>(x, wg);
    k_offsets<<<1, 32>>>();
    k_scatter<<<8, 256>>>();

    dim3 g13(INTER / BN, NTOK / BM, NUM_EXPERTS);   // 16 x 16 x 8
    k_gemm<0, HIDDEN, INTER><<<g13, 256, SMEM_DYN>>>(x, w1, nullptr);
    k_gemm<1, HIDDEN, INTER><<<g13, 256, SMEM_DYN>>>(x, w3, nullptr);
    dim3 g2(HIDDEN / BN, NTOK / BM, NUM_EXPERTS);   // 4 x 16 x 8
    k_gemm<2, INTER, HIDDEN><<<g2, 256, SMEM_DYN>>>(nullptr, w2, out);
}

// round 6
// speedup vs baseline: 1.1356x; 1.1356x over previous
#include <cuda_runtime.h>
#include <cuda_fp16.h>
#include <cstdint>

#define NUM_EXPERTS 8
#define HIDDEN 1024
#define INTER 4096
#define NTOK 2048
#define SOFTCAPV 30.0f
#define MAXROWS (NTOK * 2)

// ---------------- scratch (device globals; no allocs allowed) ----------------
__device__ int   g_counts[NUM_EXPERTS];
__device__ int   g_base[NUM_EXPERTS];
__device__ int   g_row_token[MAXROWS];
__device__ float g_row_weight[MAXROWS];
__device__ int   g_tok_e[NTOK * 2];
__device__ float g_tok_w[NTOK * 2];
__device__ float g_scratch[(size_t)MAXROWS * INTER];   // 64 MB act buffer

// ---------------- helpers ----------------
__device__ __forceinline__ void mma_f16(float* c, const uint32_t* a, const uint32_t* b) {
    asm volatile(
        "mma.sync.aligned.m16n8k16.row.col.f32.f16.f16.f32 "
        "{%0,%1,%2,%3},{%4,%5,%6,%7},{%8,%9},{%0,%1,%2,%3};"
        : "+f"(c[0]), "+f"(c[1]), "+f"(c[2]), "+f"(c[3])
        : "r"(a[0]), "r"(a[1]), "r"(a[2]), "r"(a[3]), "r"(b[0]), "r"(b[1]));
}
__device__ __forceinline__ uint32_t f2h2(float a, float b) {
    uint32_t r;
    asm("cvt.rn.f16x2.f32 %0, %1, %2;" : "=r"(r) : "f"(b), "f"(a));
    return r;
}

// ---------------- setup: zero output + router (no global atomics) ------------
__global__ void k_setup(const float* __restrict__ x, const float* __restrict__ wg,
                        float* __restrict__ out) {
    int gtid = blockIdx.x * blockDim.x + threadIdx.x;   // 65536 threads
    // zero out: 2048*1024 floats = 524288 float4 / 65536 = 8 each
    float4* o4 = (float4*)out;
#pragma unroll
    for (int j = 0; j < 8; j++)
        o4[gtid * 8 + j] = make_float4(0.f, 0.f, 0.f, 0.f);

    int warp = gtid >> 5;            // 2048 warps = tokens
    int lane = threadIdx.x & 31;
    const float* xr = x + (size_t)warp * HIDDEN;
    float acc[NUM_EXPERTS];
#pragma unroll
    for (int e = 0; e < NUM_EXPERTS; e++) acc[e] = 0.f;
    for (int h = lane; h < HIDDEN; h += 32) {
        float xv = xr[h];
#pragma unroll
        for (int e = 0; e < NUM_EXPERTS; e++) acc[e] += xv * wg[e * HIDDEN + h];
    }
#pragma unroll
    for (int off = 16; off; off >>= 1)
#pragma unroll
        for (int e = 0; e < NUM_EXPERTS; e++)
            acc[e] += __shfl_xor_sync(0xffffffffu, acc[e], off);
    if (lane == 0) {
        float l[NUM_EXPERTS];
#pragma unroll
        for (int e = 0; e < NUM_EXPERTS; e++)
            l[e] = SOFTCAPV * tanhf(acc[e] / SOFTCAPV);
        int b = 0; float vb = l[0];
#pragma unroll
        for (int e = 1; e < NUM_EXPERTS; e++) if (l[e] > vb) { b = e; vb = l[e]; }
        int s = -1; float vs = -1e30f;
#pragma unroll
        for (int e = 0; e < NUM_EXPERTS; e++)
            if (e != b && l[e] > vs) { s = e; vs = l[e]; }
        float wa = 1.f / (1.f + expf(vs - vb));   // 2-way softmax == softmax+renorm
        g_tok_e[2 * warp]     = b;  g_tok_w[2 * warp]     = wa;
        g_tok_e[2 * warp + 1] = s;  g_tok_w[2 * warp + 1] = 1.f - wa;
    }
}

// ---------------- plan: counts + prefix + scatter (single block) -------------
__global__ void k_plan() {
    __shared__ int sc[NUM_EXPERTS], sb[NUM_EXPERTS], sf[NUM_EXPERTS];
    int tid = threadIdx.x;
    if (tid < NUM_EXPERTS) { sc[tid] = 0; sf[tid] = 0; }
    __syncthreads();
    for (int i = tid; i < 2 * NTOK; i += blockDim.x)
        atomicAdd(&sc[g_tok_e[i]], 1);
    __syncthreads();
    if (tid == 0) {
        int acc = 0;
        for (int e = 0; e < NUM_EXPERTS; e++) {
            sb[e] = acc; g_base[e] = acc; g_counts[e] = sc[e]; acc += sc[e];
        }
    }
    __syncthreads();
    for (int i = tid; i < 2 * NTOK; i += blockDim.x) {
        int e = g_tok_e[i];
        int p = atomicAdd(&sf[e], 1);
        int r = sb[e] + p;
        g_row_token[r]  = i >> 1;
        g_row_weight[r] = g_tok_w[i];
    }
}

// ---------------- fp16 mma.sync grouped GEMM ----------------
#define BM 128
#define BN 128
#define BK 32
#define BKH 40          // halves per smem row (32 + 8 pad) -> 80B rows, conflict-free frags

// MODE 0: h1 = gather(x) @ w1^T -> scratch
// MODE 1: h3 = gather(x) @ w3^T ; scratch = gelu(scratch) * h3
// MODE 2: C  = scratch @ w2^T ; out[token] += weight * C (atomic)
template <int MODE, int KDIM, int NDIM>
__global__ void __launch_bounds__(512, 2) k_gemm(const float* __restrict__ Asrc,
                                                 const float* __restrict__ W,
                                                 float* __restrict__ Out) {
    int e   = blockIdx.z;
    int cnt = g_counts[e];
    int m0  = blockIdx.x * BM;          // m fastest -> concurrent CTAs share B tile in L2
    if (m0 >= cnt) return;
    int n0    = blockIdx.y * BN;
    int rbase = g_base[e];
    const float* Ap = (MODE == 2) ? (const float*)g_scratch : Asrc;
    const float* B  = W + (size_t)e * NDIM * KDIM;

    __shared__ __align__(16) __half Ah[2][BM][BKH];
    __shared__ __align__(16) __half Bh[2][BN][BKH];

    int tid  = threadIdx.x;
    int lane = tid & 31, warp = tid >> 5;       // 16 warps: 4(m) x 4(n), tile 32x32
    int wm = warp & 3, wn = warp >> 2;
    int g = lane >> 2, tg = lane & 3;

    // ---- loader: 4 chunks of 16B (4 f32) per thread per stage ----
    const float* ptr[4]; int row[4], ch[4], va[4], isA[4];
#pragma unroll
    for (int p = 0; p < 4; p++) {
        int id = tid + p * 512;
        if (id < 1024) {            // A: 128 rows x 8 chunks
            int r = id >> 3, c = id & 7;
            isA[p] = 1; row[p] = r; ch[p] = c;
            int mg = m0 + r;
            if (MODE == 2) {
                int rr = rbase + (mg < cnt ? mg : 0);
                ptr[p] = Ap + (size_t)rr * KDIM + c * 4;
            } else {
                int t = (mg < cnt) ? g_row_token[rbase + mg] : 0;
                ptr[p] = Ap + (size_t)t * KDIM + c * 4;
            }
            va[p] = (mg < cnt);
        } else {                    // B: 128 rows x 8 chunks
            int id2 = id - 1024;
            int r = id2 >> 3, c = id2 & 7;
            isA[p] = 0; row[p] = r; ch[p] = c;
            ptr[p] = B + (size_t)(n0 + r) * KDIM + c * 4;
            va[p] = 1;
        }
    }

    float4 G[4];
    auto gload = [&](int kt) {
        int k0 = kt * BK;
#pragma unroll
        for (int p = 0; p < 4; p++)
            G[p] = va[p] ? *(const float4*)(ptr[p] + k0)
                         : make_float4(0.f, 0.f, 0.f, 0.f);
    };
    auto gstore = [&](int s) {
#pragma unroll
        for (int p = 0; p < 4; p++) {
            uint2 h = make_uint2(f2h2(G[p].x, G[p].y), f2h2(G[p].z, G[p].w));
            __half* dst = isA[p] ? &Ah[s][row[p]][ch[p] * 4]
                                 : &Bh[s][row[p]][ch[p] * 4];
            *(uint2*)dst = h;
        }
    };

    float acc[2][4][4];
#pragma unroll
    for (int i = 0; i < 2; i++)
#pragma unroll
        for (int j = 0; j < 4; j++)
#pragma unroll
            for (int c = 0; c < 4; c++) acc[i][j][c] = 0.f;

    constexpr int KT = KDIM / BK;
    gload(0);
    for (int kt = 0; kt < KT; kt++) {
        int s = kt & 1;
        __syncthreads();            // f16[s] consumers (iter kt-2) are done
        gstore(s);
        if (kt + 1 < KT) gload(kt + 1);
        __syncthreads();            // f16[s] ready
#pragma unroll
        for (int kk = 0; kk < BK; kk += 16) {
            uint32_t af[2][4], bf[4][2];
#pragma unroll
            for (int mt = 0; mt < 2; mt++) {
                int r = wm * 32 + mt * 16;
                af[mt][0] = *(const uint32_t*)&Ah[s][r + g][kk + 2 * tg];
                af[mt][1] = *(const uint32_t*)&Ah[s][r + g + 8][kk + 2 * tg];
                af[mt][2] = *(const uint32_t*)&Ah[s][r + g][kk + 2 * tg + 8];
                af[mt][3] = *(const uint32_t*)&Ah[s][r + g + 8][kk + 2 * tg + 8];
            }
#pragma unroll
            for (int nt = 0; nt < 4; nt++) {
                int c = wn * 32 + nt * 8;
                bf[nt][0] = *(const uint32_t*)&Bh[s][c + g][kk + 2 * tg];
                bf[nt][1] = *(const uint32_t*)&Bh[s][c + g][kk + 2 * tg + 8];
            }
#pragma unroll
            for (int mt = 0; mt < 2; mt++)
#pragma unroll
                for (int nt = 0; nt < 4; nt++)
                    mma_f16(acc[mt][nt], af[mt], bf[nt]);
        }
    }

    // ---- epilogue ----
#pragma unroll
    for (int mt = 0; mt < 2; mt++) {
#pragma unroll
        for (int nt = 0; nt < 4; nt++) {
#pragma unroll
            for (int cr = 0; cr < 4; cr++) {
                int rrow = wm * 32 + mt * 16 + g + ((cr >> 1) ? 8 : 0);
                int mg = m0 + rrow;
                if (mg >= cnt) continue;
                int col = n0 + wn * 32 + nt * 8 + tg * 2 + (cr & 1);
                float v = acc[mt][nt][cr];
                if (MODE == 0) {
                    g_scratch[(size_t)(rbase + mg) * INTER + col] = v;
                } else if (MODE == 1) {
                    size_t idx = (size_t)(rbase + mg) * INTER + col;
                    float h1 = g_scratch[idx];
                    float ge = 0.5f * h1 * (1.f + erff(h1 * 0.70710678118654752f));
                    g_scratch[idx] = ge * v;
                } else {
                    int t  = g_row_token[rbase + mg];
                    float w = g_row_weight[rbase + mg];
                    atomicAdd(&Out[(size_t)t * HIDDEN + col], w * v);
                }
            }
        }
    }
}

// ---------------- launch ----------------
extern "C" void kernel_launch(void* const* d_in, const int* in_sizes, int n_in,
                              void* d_out, int out_size) {
    const float* x  = (const float*)d_in[0];
    const float* wg = (const float*)d_in[1];
    const float* w1 = (const float*)d_in[2];
    const float* w3 = (const float*)d_in[3];
    const float* w2 = (const float*)d_in[4];
    float* out = (float*)d_out;

    k_setup<<<256, 256>>>(x, wg, out);
    k_plan<<<1, 512>>>();

    dim3 g13(NTOK / BM, INTER / BN, NUM_EXPERTS);   // m fastest: 16 x 32 x 8
    k_gemm<0, HIDDEN, INTER><<<g13, 512>>>(x, w1, nullptr);
    k_gemm<1, HIDDEN, INTER><<<g13, 512>>>(x, w3, nullptr);
    dim3 g2(NTOK / BM, HIDDEN / BN, NUM_EXPERTS);   // 16 x 8 x 8
    k_gemm<2, INTER, HIDDEN><<<g2, 512>>>(nullptr, w2, out);
}

// round 11
// speedup vs baseline: 1.7230x; 1.5172x over previous
#include <cuda_runtime.h>
#include <cuda_fp16.h>
#include <cstdint>

#define NUM_EXPERTS 8
#define HIDDEN 1024
#define INTER 4096
#define NTOK 2048
#define SOFTCAPV 30.0f
#define MAXROWS (NTOK * 2)

// ---------------- scratch (device globals; no allocs allowed) ----------------
__device__ int    g_counts[NUM_EXPERTS];
__device__ int    g_base[NUM_EXPERTS];
__device__ int    g_row_token[MAXROWS];
__device__ float  g_row_weight[MAXROWS];
__device__ int    g_tok_e[NTOK * 2];
__device__ float  g_tok_w[NTOK * 2];
__device__ __align__(16) __half g_w1h[(size_t)NUM_EXPERTS * INTER * HIDDEN];  // 64 MB
__device__ __align__(16) __half g_w3h[(size_t)NUM_EXPERTS * INTER * HIDDEN];  // 64 MB
__device__ __align__(16) __half g_w2h[(size_t)NUM_EXPERTS * HIDDEN * INTER];  // 64 MB
__device__ __align__(16) __half g_xh[(size_t)NTOK * HIDDEN];                  // 4 MB
__device__ __align__(16) __half g_act[(size_t)MAXROWS * INTER];               // 32 MB

// ---------------- helpers ----------------
__device__ __forceinline__ void mma_f16(float* c, const uint32_t* a, const uint32_t* b) {
    asm volatile(
        "mma.sync.aligned.m16n8k16.row.col.f32.f16.f16.f32 "
        "{%0,%1,%2,%3},{%4,%5,%6,%7},{%8,%9},{%0,%1,%2,%3};"
        : "+f"(c[0]), "+f"(c[1]), "+f"(c[2]), "+f"(c[3])
        : "r"(a[0]), "r"(a[1]), "r"(a[2]), "r"(a[3]), "r"(b[0]), "r"(b[1]));
}
__device__ __forceinline__ uint32_t f2h2(float a, float b) {
    uint32_t r;
    asm("cvt.rn.f16x2.f32 %0, %1, %2;" : "=r"(r) : "f"(b), "f"(a));
    return r;
}
__device__ __forceinline__ void cp_async16(uint32_t dst, const void* src, int src_sz) {
    asm volatile("cp.async.cg.shared.global [%0], [%1], 16, %2;\n"
                 :: "r"(dst), "l"(src), "r"(src_sz));
}
__device__ __forceinline__ uint32_t smem_u32(const void* p) {
    uint32_t a;
    asm("{ .reg .u64 t; cvta.to.shared.u64 t, %1; cvt.u32.u64 %0, t; }"
        : "=r"(a) : "l"(p));
    return a;
}
__device__ __forceinline__ void ldsm4(uint32_t* r, uint32_t addr) {
    asm volatile("ldmatrix.sync.aligned.m8n8.x4.shared.b16 {%0,%1,%2,%3}, [%4];"
                 : "=r"(r[0]), "=r"(r[1]), "=r"(r[2]), "=r"(r[3]) : "r"(addr));
}

// ---------------- f32 -> f16 bulk convert (dst selected by template) ---------
template <int SEL>
__global__ void k_cvt(const float4* __restrict__ src, int n4) {
    uint2* dst = (SEL == 0) ? (uint2*)g_w1h
               : (SEL == 1) ? (uint2*)g_w3h
               : (SEL == 2) ? (uint2*)g_w2h
                            : (uint2*)g_xh;
    int i = blockIdx.x * blockDim.x + threadIdx.x;
    int stride = gridDim.x * blockDim.x;
    for (; i < n4; i += stride) {
        float4 v = src[i];
        dst[i] = make_uint2(f2h2(v.x, v.y), f2h2(v.z, v.w));
    }
}

// ---------------- setup: zero output + router ----------------
__global__ void k_setup(const float* __restrict__ x, const float* __restrict__ wg,
                        float* __restrict__ out) {
    int gtid = blockIdx.x * blockDim.x + threadIdx.x;   // 65536 threads
    float4* o4 = (float4*)out;
#pragma unroll
    for (int j = 0; j < 8; j++)
        o4[gtid * 8 + j] = make_float4(0.f, 0.f, 0.f, 0.f);

    int warp = gtid >> 5;            // 2048 warps = tokens
    int lane = threadIdx.x & 31;
    const float* xr = x + (size_t)warp * HIDDEN;
    float acc[NUM_EXPERTS];
#pragma unroll
    for (int e = 0; e < NUM_EXPERTS; e++) acc[e] = 0.f;
    for (int h = lane; h < HIDDEN; h += 32) {
        float xv = xr[h];
#pragma unroll
        for (int e = 0; e < NUM_EXPERTS; e++) acc[e] += xv * wg[e * HIDDEN + h];
    }
#pragma unroll
    for (int off = 16; off; off >>= 1)
#pragma unroll
        for (int e = 0; e < NUM_EXPERTS; e++)
            acc[e] += __shfl_xor_sync(0xffffffffu, acc[e], off);
    if (lane == 0) {
        float l[NUM_EXPERTS];
#pragma unroll
        for (int e = 0; e < NUM_EXPERTS; e++)
            l[e] = SOFTCAPV * tanhf(acc[e] / SOFTCAPV);
        int b = 0; float vb = l[0];
#pragma unroll
        for (int e = 1; e < NUM_EXPERTS; e++) if (l[e] > vb) { b = e; vb = l[e]; }
        int s = -1; float vs = -1e30f;
#pragma unroll
        for (int e = 0; e < NUM_EXPERTS; e++)
            if (e != b && l[e] > vs) { s = e; vs = l[e]; }
        float wa = 1.f / (1.f + expf(vs - vb));   // 2-way softmax == softmax+renorm
        g_tok_e[2 * warp]     = b;  g_tok_w[2 * warp]     = wa;
        g_tok_e[2 * warp + 1] = s;  g_tok_w[2 * warp + 1] = 1.f - wa;
    }
}

// ---------------- plan: counts + prefix + scatter (single block) -------------
__global__ void k_plan() {
    __shared__ int sc[NUM_EXPERTS], sb[NUM_EXPERTS], sf[NUM_EXPERTS];
    int tid = threadIdx.x;
    if (tid < NUM_EXPERTS) { sc[tid] = 0; sf[tid] = 0; }
    __syncthreads();
    for (int i = tid; i < 2 * NTOK; i += blockDim.x)
        atomicAdd(&sc[g_tok_e[i]], 1);
    __syncthreads();
    if (tid == 0) {
        int acc = 0;
        for (int e = 0; e < NUM_EXPERTS; e++) {
            sb[e] = acc; g_base[e] = acc; g_counts[e] = sc[e]; acc += sc[e];
        }
    }
    __syncthreads();
    for (int i = tid; i < 2 * NTOK; i += blockDim.x) {
        int e = g_tok_e[i];
        int p = atomicAdd(&sf[e], 1);
        int r = sb[e] + p;
        g_row_token[r]  = i >> 1;
        g_row_weight[r] = g_tok_w[i];
    }
}

// ---------------- f16 ldmatrix GEMM ----------------
#define BM 128
#define BN 256
#define BK 32
#define NSTAGE 3
#define A_ST (BM * BK * 2)          // 8192 B
#define B_ST (BN * BK * 2)          // 16384 B
#define STG (A_ST + B_ST)           // 24576 B
#define SMEM_DYN (NSTAGE * STG)     // 73728 B

// swizzled chunk byte offset inside a tile: row, ch(0..3) of 16B
__device__ __forceinline__ uint32_t swz(int row, int ch) {
    return (uint32_t)(row * 64 + ((ch ^ ((row >> 1) & 3)) << 4));
}

// MODE 0: h1 = gather(xh) @ w1h^T -> g_act (f16)
// MODE 1: h3 = gather(xh) @ w3h^T ; g_act = gelu(g_act) * h3 (f16)
// MODE 2: C  = g_act @ w2h^T ; out[token] += weight * C (f32 atomic)
template <int MODE, int KDIM, int NDIM>
__global__ void __launch_bounds__(256, 1) k_gemm(float* __restrict__ Out) {
    const __half* __restrict__ Ain = (MODE == 2) ? g_act : g_xh;
    const __half* __restrict__ Wsrc = (MODE == 0) ? g_w1h
                                    : (MODE == 1) ? g_w3h : g_w2h;
    int e   = blockIdx.z;
    int cnt = g_counts[e];
    int m0  = blockIdx.x * BM;          // m fastest: concurrent CTAs share B in L2
    if (m0 >= cnt) return;
    int n0    = blockIdx.y * BN;
    int rbase = g_base[e];
    const __half* B = Wsrc + (size_t)e * NDIM * KDIM;

    extern __shared__ __align__(16) char smem[];
    uint32_t sbase = smem_u32(smem);

    int tid  = threadIdx.x;
    int lane = tid & 31, warp = tid >> 5;       // 8 warps: 2(m) x 4(n), tile 64x64
    int wm = warp & 1, wn = warp >> 1;

    // ---- loader: 6 chunks of 16B per thread per stage (A:2, B:4) ----
    const __half* aptr[2]; int asz[2]; uint32_t aoff[2];
#pragma unroll
    for (int p = 0; p < 2; p++) {
        int id  = tid + p * 256;        // 0..511
        int row = id >> 2, ch = id & 3;
        int mg  = m0 + row;
        if (MODE == 2) {
            int rr = rbase + (mg < cnt ? mg : 0);
            aptr[p] = Ain + (size_t)rr * KDIM + ch * 8;
        } else {
            int t = (mg < cnt) ? g_row_token[rbase + mg] : 0;
            aptr[p] = Ain + (size_t)t * KDIM + ch * 8;
        }
        asz[p]  = (mg < cnt) ? 16 : 0;
        aoff[p] = swz(row, ch);
    }
    const __half* bptr[4]; uint32_t boff[4];
#pragma unroll
    for (int p = 0; p < 4; p++) {
        int id  = tid + p * 256;        // 0..1023
        int row = id >> 2, ch = id & 3;
        bptr[p] = B + (size_t)(n0 + row) * KDIM + ch * 8;
        boff[p] = swz(row, ch);
    }

    auto issue = [&](int kt, int st) {
        uint32_t sA = sbase + st * STG;
        uint32_t sB = sA + A_ST;
        int k0 = kt * BK;
#pragma unroll
        for (int p = 0; p < 2; p++) cp_async16(sA + aoff[p], aptr[p] + k0, asz[p]);
#pragma unroll
        for (int p = 0; p < 4; p++) cp_async16(sB + boff[p], bptr[p] + k0, 16);
        asm volatile("cp.async.commit_group;\n");
    };

    // ---- ldmatrix lane addressing (lane-const parts) ----
    int q  = lane >> 3;                  // matrix index 0..3
    int qr = (q & 1) * 8 + (lane & 7);   // row within 16-row group
    int cq = q >> 1;                     // k-chunk select
    int rA0 = wm * 64 + qr;
    int rB0 = wn * 64 + qr;
    int swzA = (rA0 >> 1) & 3;
    int swzB = (rB0 >> 1) & 3;
    uint32_t offA[2], offB[2];
#pragma unroll
    for (int kk = 0; kk < 2; kk++) {
        offA[kk] = (uint32_t)(rA0 * 64 + (((2 * kk + cq) ^ swzA) << 4));
        offB[kk] = (uint32_t)(rB0 * 64 + (((2 * kk + cq) ^ swzB) << 4));
    }

    float acc[4][8][4];
#pragma unroll
    for (int i = 0; i < 4; i++)
#pragma unroll
        for (int j = 0; j < 8; j++)
#pragma unroll
            for (int c = 0; c < 4; c++) acc[i][j][c] = 0.f;

    constexpr int KT = KDIM / BK;
    issue(0, 0);
    issue(1, 1);
    int s = 0;
    for (int kt = 0; kt < KT; kt++) {
        int s2 = (s >= 1) ? s - 1 : 2;      // (s+2)%3
        if (kt + 2 < KT) {
            issue(kt + 2, s2);
            asm volatile("cp.async.wait_group 2;\n" ::: "memory");
        } else if (kt + 1 < KT) {
            asm volatile("cp.async.wait_group 1;\n" ::: "memory");
        } else {
            asm volatile("cp.async.wait_group 0;\n" ::: "memory");
        }
        __syncthreads();

        uint32_t aS = sbase + s * STG;
        uint32_t bS = aS + A_ST;
#pragma unroll
        for (int kk = 0; kk < 2; kk++) {
            uint32_t a[4][4], b[8][2];
#pragma unroll
            for (int mt = 0; mt < 4; mt++)
                ldsm4(a[mt], aS + offA[kk] + mt * 1024);
#pragma unroll
            for (int g2 = 0; g2 < 4; g2++) {
                uint32_t r[4];
                ldsm4(r, bS + offB[kk] + g2 * 1024);
                b[2 * g2][0] = r[0]; b[2 * g2][1] = r[2];
                b[2 * g2 + 1][0] = r[1]; b[2 * g2 + 1][1] = r[3];
            }
#pragma unroll
            for (int mt = 0; mt < 4; mt++)
#pragma unroll
                for (int nt = 0; nt < 8; nt++)
                    mma_f16(acc[mt][nt], a[mt], b[nt]);
        }
        __syncthreads();
        s = (s == 2) ? 0 : s + 1;
    }

    // ---- epilogue ----
    int lr = lane >> 2, lc = lane & 3;
#pragma unroll
    for (int mt = 0; mt < 4; mt++) {
#pragma unroll
        for (int rh = 0; rh < 2; rh++) {
            int row = wm * 64 + mt * 16 + lr + rh * 8;
            int mg  = m0 + row;
            if (mg >= cnt) continue;
            int gr = rbase + mg;
            int t = 0; float wgt = 0.f;
            if (MODE == 2) { t = g_row_token[gr]; wgt = g_row_weight[gr]; }
#pragma unroll
            for (int nt = 0; nt < 8; nt++) {
                int col = n0 + wn * 64 + nt * 8 + lc * 2;
                float v0 = acc[mt][nt][2 * rh];
                float v1 = acc[mt][nt][2 * rh + 1];
                if (MODE == 0) {
                    *(uint32_t*)&g_act[(size_t)gr * INTER + col] = f2h2(v0, v1);
                } else if (MODE == 1) {
                    uint32_t* pp = (uint32_t*)&g_act[(size_t)gr * INTER + col];
                    __half2 h1 = *(__half2*)pp;
                    float a0 = __low2float(h1), a1 = __high2float(h1);
                    float g0 = 0.5f * a0 * (1.f + erff(a0 * 0.70710678118654752f));
                    float g1 = 0.5f * a1 * (1.f + erff(a1 * 0.70710678118654752f));
                    *pp = f2h2(g0 * v0, g1 * v1);
                } else {
                    float* op = Out + (size_t)t * HIDDEN + col;
                    atomicAdd(op, wgt * v0);
                    atomicAdd(op + 1, wgt * v1);
                }
            }
        }
    }
}

// ---------------- launch ----------------
extern "C" void kernel_launch(void* const* d_in, const int* in_sizes, int n_in,
                              void* d_out, int out_size) {
    const float* x  = (const float*)d_in[0];
    const float* wg = (const float*)d_in[1];
    const float* w1 = (const float*)d_in[2];
    const float* w3 = (const float*)d_in[3];
    const float* w2 = (const float*)d_in[4];
    float* out = (float*)d_out;

    cudaFuncSetAttribute(k_gemm<0, HIDDEN, INTER>,
                         cudaFuncAttributeMaxDynamicSharedMemorySize, SMEM_DYN);
    cudaFuncSetAttribute(k_gemm<1, HIDDEN, INTER>,
                         cudaFuncAttributeMaxDynamicSharedMemorySize, SMEM_DYN);
    cudaFuncSetAttribute(k_gemm<2, INTER, HIDDEN>,
                         cudaFuncAttributeMaxDynamicSharedMemorySize, SMEM_DYN);

    const int W4 = NUM_EXPERTS * INTER * HIDDEN / 4;   // 8M float4
    k_cvt<0><<<2048, 256>>>((const float4*)w1, W4);
    k_cvt<1><<<2048, 256>>>((const float4*)w3, W4);
    k_cvt<2><<<2048, 256>>>((const float4*)w2, W4);
    k_cvt<3><<<1024, 256>>>((const float4*)x, NTOK * HIDDEN / 4);

    k_setup<<<256, 256>>>(x, wg, out);
    k_plan<<<1, 512>>>();

    dim3 g13(NTOK / BM, INTER / BN, NUM_EXPERTS);   // 16 x 16 x 8
    k_gemm<0, HIDDEN, INTER><<<g13, 256, SMEM_DYN>>>(nullptr);
    k_gemm<1, HIDDEN, INTER><<<g13, 256, SMEM_DYN>>>(nullptr);
    dim3 g2(NTOK / BM, HIDDEN / BN, NUM_EXPERTS);   // 16 x 4 x 8
    k_gemm<2, INTER, HIDDEN><<<g2, 256, SMEM_DYN>>>(out);
}

// round 12
// speedup vs baseline: 1.8661x; 1.0831x over previous
#include <cuda_runtime.h>
#include <cuda_fp16.h>
#include <cstdint>

#define NUM_EXPERTS 8
#define HIDDEN 1024
#define INTER 4096
#define NTOK 2048
#define SOFTCAPV 30.0f
#define MAXROWS (NTOK * 2)

// ---------------- scratch (device globals; no allocs allowed) ----------------
__device__ int    g_counts[NUM_EXPERTS];
__device__ int    g_base[NUM_EXPERTS];
__device__ int    g_row_token[MAXROWS];
__device__ float  g_row_weight[MAXROWS];
__device__ int    g_tok_e[NTOK * 2];
__device__ float  g_tok_w[NTOK * 2];
__device__ __align__(16) __half g_w1h[(size_t)NUM_EXPERTS * INTER * HIDDEN];  // 64 MB
__device__ __align__(16) __half g_w3h[(size_t)NUM_EXPERTS * INTER * HIDDEN];  // 64 MB
__device__ __align__(16) __half g_w2h[(size_t)NUM_EXPERTS * HIDDEN * INTER];  // 64 MB
__device__ __align__(16) __half g_xh[(size_t)NTOK * HIDDEN];                  // 4 MB
__device__ __align__(16) __half g_act[(size_t)MAXROWS * INTER];               // 32 MB

// ---------------- helpers ----------------
__device__ __forceinline__ void mma_f16(float* c, const uint32_t* a, const uint32_t* b) {
    asm volatile(
        "mma.sync.aligned.m16n8k16.row.col.f32.f16.f16.f32 "
        "{%0,%1,%2,%3},{%4,%5,%6,%7},{%8,%9},{%0,%1,%2,%3};"
        : "+f"(c[0]), "+f"(c[1]), "+f"(c[2]), "+f"(c[3])
        : "r"(a[0]), "r"(a[1]), "r"(a[2]), "r"(a[3]), "r"(b[0]), "r"(b[1]));
}
__device__ __forceinline__ uint32_t f2h2(float a, float b) {
    uint32_t r;
    asm("cvt.rn.f16x2.f32 %0, %1, %2;" : "=r"(r) : "f"(b), "f"(a));
    return r;
}
__device__ __forceinline__ void cp_async16(uint32_t dst, const void* src, int src_sz) {
    asm volatile("cp.async.cg.shared.global [%0], [%1], 16, %2;\n"
                 :: "r"(dst), "l"(src), "r"(src_sz));
}
__device__ __forceinline__ uint32_t smem_u32(const void* p) {
    uint32_t a;
    asm("{ .reg .u64 t; cvta.to.shared.u64 t, %1; cvt.u32.u64 %0, t; }"
        : "=r"(a) : "l"(p));
    return a;
}
__device__ __forceinline__ void ldsm4(uint32_t* r, uint32_t addr) {
    asm volatile("ldmatrix.sync.aligned.m8n8.x4.shared.b16 {%0,%1,%2,%3}, [%4];"
                 : "=r"(r[0]), "=r"(r[1]), "=r"(r[2]), "=r"(r[3]) : "r"(addr));
}
__device__ __forceinline__ float gelu_exact(float v) {
    return 0.5f * v * (1.f + erff(v * 0.70710678118654752f));
}

// ---------------- f32 -> f16 bulk convert (dst selected by template) ---------
template <int SEL>
__global__ void k_cvt(const float4* __restrict__ src, int n4) {
    uint2* dst = (SEL == 0) ? (uint2*)g_w1h
               : (SEL == 1) ? (uint2*)g_w3h
               : (SEL == 2) ? (uint2*)g_w2h
                            : (uint2*)g_xh;
    int i = blockIdx.x * blockDim.x + threadIdx.x;
    int stride = gridDim.x * blockDim.x;
    for (; i < n4; i += stride) {
        float4 v = src[i];
        dst[i] = make_uint2(f2h2(v.x, v.y), f2h2(v.z, v.w));
    }
}

// ---------------- setup: zero output + router ----------------
__global__ void k_setup(const float* __restrict__ x, const float* __restrict__ wg,
                        float* __restrict__ out) {
    int gtid = blockIdx.x * blockDim.x + threadIdx.x;   // 65536 threads
    float4* o4 = (float4*)out;
#pragma unroll
    for (int j = 0; j < 8; j++)
        o4[gtid * 8 + j] = make_float4(0.f, 0.f, 0.f, 0.f);

    int warp = gtid >> 5;            // 2048 warps = tokens
    int lane = threadIdx.x & 31;
    const float* xr = x + (size_t)warp * HIDDEN;
    float acc[NUM_EXPERTS];
#pragma unroll
    for (int e = 0; e < NUM_EXPERTS; e++) acc[e] = 0.f;
    for (int h = lane; h < HIDDEN; h += 32) {
        float xv = xr[h];
#pragma unroll
        for (int e = 0; e < NUM_EXPERTS; e++) acc[e] += xv * wg[e * HIDDEN + h];
    }
#pragma unroll
    for (int off = 16; off; off >>= 1)
#pragma unroll
        for (int e = 0; e < NUM_EXPERTS; e++)
            acc[e] += __shfl_xor_sync(0xffffffffu, acc[e], off);
    if (lane == 0) {
        float l[NUM_EXPERTS];
#pragma unroll
        for (int e = 0; e < NUM_EXPERTS; e++)
            l[e] = SOFTCAPV * tanhf(acc[e] / SOFTCAPV);
        int b = 0; float vb = l[0];
#pragma unroll
        for (int e = 1; e < NUM_EXPERTS; e++) if (l[e] > vb) { b = e; vb = l[e]; }
        int s = -1; float vs = -1e30f;
#pragma unroll
        for (int e = 0; e < NUM_EXPERTS; e++)
            if (e != b && l[e] > vs) { s = e; vs = l[e]; }
        float wa = 1.f / (1.f + expf(vs - vb));   // 2-way softmax == softmax+renorm
        g_tok_e[2 * warp]     = b;  g_tok_w[2 * warp]     = wa;
        g_tok_e[2 * warp + 1] = s;  g_tok_w[2 * warp + 1] = 1.f - wa;
    }
}

// ---------------- plan: counts + prefix + scatter (single block) -------------
__global__ void k_plan() {
    __shared__ int sc[NUM_EXPERTS], sb[NUM_EXPERTS], sf[NUM_EXPERTS];
    int tid = threadIdx.x;
    if (tid < NUM_EXPERTS) { sc[tid] = 0; sf[tid] = 0; }
    __syncthreads();
    for (int i = tid; i < 2 * NTOK; i += blockDim.x)
        atomicAdd(&sc[g_tok_e[i]], 1);
    __syncthreads();
    if (tid == 0) {
        int acc = 0;
        for (int e = 0; e < NUM_EXPERTS; e++) {
            sb[e] = acc; g_base[e] = acc; g_counts[e] = sc[e]; acc += sc[e];
        }
    }
    __syncthreads();
    for (int i = tid; i < 2 * NTOK; i += blockDim.x) {
        int e = g_tok_e[i];
        int p = atomicAdd(&sf[e], 1);
        int r = sb[e] + p;
        g_row_token[r]  = i >> 1;
        g_row_weight[r] = g_tok_w[i];
    }
}

// ---------------- tiling ----------------
#define BM 128
#define BN 128
#define BK 32
#define NSTAGE 3
#define A_ST (BM * BK * 2)            // 8192 B
#define B_ST (BN * BK * 2)            // 8192 B
#define STG13 (A_ST + 2 * B_ST)       // 24576 B
#define SMEM13 (NSTAGE * STG13)       // 73728 B
#define STG2 (A_ST + B_ST)            // 16384 B
#define SMEM2 (NSTAGE * STG2)         // 49152 B

// swizzled chunk byte offset inside a tile: row, ch(0..3) of 16B (64B rows)
__device__ __forceinline__ uint32_t swz(int row, int ch) {
    return (uint32_t)(row * 64 + ((ch ^ ((row >> 1) & 3)) << 4));
}

// ---------------- fused up-proj: g_act = gelu(x@w1^T) * (x@w3^T) -------------
__global__ void __launch_bounds__(256, 1) k_gemm13() {
    int e   = blockIdx.z;
    int cnt = g_counts[e];
    int m0  = blockIdx.x * BM;          // m fastest: concurrent CTAs share B in L2
    if (m0 >= cnt) return;
    int n0    = blockIdx.y * BN;
    int rbase = g_base[e];
    const __half* B1 = g_w1h + (size_t)e * INTER * HIDDEN;
    const __half* B3 = g_w3h + (size_t)e * INTER * HIDDEN;

    extern __shared__ __align__(16) char smem[];
    uint32_t sbase = smem_u32(smem);

    int tid  = threadIdx.x;
    int lane = tid & 31, warp = tid >> 5;   // 8 warps: 2(m) x 4(n); tile 64x32 per B
    int wm = warp & 1, wn = warp >> 1;

    // ---- loader: per thread per stage, 16B chunks: A x2, B1 x2, B3 x2 ----
    const __half* aptr[2]; int asz[2]; uint32_t coff[2];
    const __half* b1ptr[2]; const __half* b3ptr[2];
#pragma unroll
    for (int p = 0; p < 2; p++) {
        int id  = tid + p * 256;        // 0..511 = 128 rows x 4 chunks
        int row = id >> 2, ch = id & 3;
        int mg  = m0 + row;
        int t = (mg < cnt) ? g_row_token[rbase + mg] : 0;
        aptr[p] = g_xh + (size_t)t * HIDDEN + ch * 8;
        asz[p]  = (mg < cnt) ? 16 : 0;
        b1ptr[p] = B1 + (size_t)(n0 + row) * HIDDEN + ch * 8;
        b3ptr[p] = B3 + (size_t)(n0 + row) * HIDDEN + ch * 8;
        coff[p] = swz(row, ch);
    }

    auto issue = [&](int kt, int st) {
        uint32_t sA  = sbase + st * STG13;
        uint32_t sB1 = sA + A_ST;
        uint32_t sB3 = sB1 + B_ST;
        int k0 = kt * BK;
#pragma unroll
        for (int p = 0; p < 2; p++) {
            cp_async16(sA + coff[p], aptr[p] + k0, asz[p]);
            cp_async16(sB1 + coff[p], b1ptr[p] + k0, 16);
            cp_async16(sB3 + coff[p], b3ptr[p] + k0, 16);
        }
        asm volatile("cp.async.commit_group;\n");
    };

    // ---- ldmatrix lane addressing ----
    int q  = lane >> 3;
    int qr = (q & 1) * 8 + (lane & 7);
    int cq = q >> 1;
    int rA0 = wm * 64 + qr;
    int rB0 = wn * 32 + qr;
    int swzA = (rA0 >> 1) & 3;
    int swzB = (rB0 >> 1) & 3;
    uint32_t offA[2], offB[2];
#pragma unroll
    for (int kk = 0; kk < 2; kk++) {
        offA[kk] = (uint32_t)(rA0 * 64 + (((2 * kk + cq) ^ swzA) << 4));
        offB[kk] = (uint32_t)(rB0 * 64 + (((2 * kk + cq) ^ swzB) << 4));
    }

    float acc1[4][4][4], acc3[4][4][4];
#pragma unroll
    for (int i = 0; i < 4; i++)
#pragma unroll
        for (int j = 0; j < 4; j++)
#pragma unroll
            for (int c = 0; c < 4; c++) { acc1[i][j][c] = 0.f; acc3[i][j][c] = 0.f; }

    uint32_t a[2][4][4], b1f[2][4][2], b3f[2][4][2];
    auto ldfrag = [&](uint32_t aS, uint32_t b1S, uint32_t b3S, int kk, int buf) {
#pragma unroll
        for (int mt = 0; mt < 4; mt++)
            ldsm4(a[buf][mt], aS + offA[kk] + mt * 1024);
#pragma unroll
        for (int g2 = 0; g2 < 2; g2++) {
            uint32_t r[4];
            ldsm4(r, b1S + offB[kk] + g2 * 1024);
            b1f[buf][2 * g2][0] = r[0]; b1f[buf][2 * g2][1] = r[2];
            b1f[buf][2 * g2 + 1][0] = r[1]; b1f[buf][2 * g2 + 1][1] = r[3];
            ldsm4(r, b3S + offB[kk] + g2 * 1024);
            b3f[buf][2 * g2][0] = r[0]; b3f[buf][2 * g2][1] = r[2];
            b3f[buf][2 * g2 + 1][0] = r[1]; b3f[buf][2 * g2 + 1][1] = r[3];
        }
    };

    constexpr int KT = HIDDEN / BK;     // 32
    issue(0, 0);
    issue(1, 1);
    int s = 0;
    for (int kt = 0; kt < KT; kt++) {
        if (kt + 1 < KT) {
            asm volatile("cp.async.wait_group 1;\n" ::: "memory");
        } else {
            asm volatile("cp.async.wait_group 0;\n" ::: "memory");
        }
        __syncthreads();
        if (kt + 2 < KT) {
            int s2 = (s >= 1) ? s - 1 : 2;      // (s+2)%3
            issue(kt + 2, s2);
        }
        uint32_t aS  = sbase + s * STG13;
        uint32_t b1S = aS + A_ST;
        uint32_t b3S = b1S + B_ST;
        ldfrag(aS, b1S, b3S, 0, 0);
        ldfrag(aS, b1S, b3S, 1, 1);
#pragma unroll
        for (int kk = 0; kk < 2; kk++)
#pragma unroll
            for (int mt = 0; mt < 4; mt++)
#pragma unroll
                for (int nt = 0; nt < 4; nt++) {
                    mma_f16(acc1[mt][nt], a[kk][mt], b1f[kk][nt]);
                    mma_f16(acc3[mt][nt], a[kk][mt], b3f[kk][nt]);
                }
        s = (s == 2) ? 0 : s + 1;
    }

    // ---- epilogue: gelu(h1)*h3 -> f16 g_act ----
    int lr = lane >> 2, lc = lane & 3;
#pragma unroll
    for (int mt = 0; mt < 4; mt++) {
#pragma unroll
        for (int rh = 0; rh < 2; rh++) {
            int row = wm * 64 + mt * 16 + lr + rh * 8;
            int mg  = m0 + row;
            if (mg >= cnt) continue;
            int gr = rbase + mg;
#pragma unroll
            for (int nt = 0; nt < 4; nt++) {
                int col = n0 + wn * 32 + nt * 8 + lc * 2;
                float h10 = acc1[mt][nt][2 * rh], h11 = acc1[mt][nt][2 * rh + 1];
                float h30 = acc3[mt][nt][2 * rh], h31 = acc3[mt][nt][2 * rh + 1];
                *(uint32_t*)&g_act[(size_t)gr * INTER + col] =
                    f2h2(gelu_exact(h10) * h30, gelu_exact(h11) * h31);
            }
        }
    }
}

// ---------------- down-proj: out[token] += w * (act @ w2^T) ------------------
__global__ void __launch_bounds__(256, 1) k_gemm2(float* __restrict__ Out) {
    int e   = blockIdx.z;
    int cnt = g_counts[e];
    int m0  = blockIdx.x * BM;
    if (m0 >= cnt) return;
    int n0    = blockIdx.y * BN;
    int rbase = g_base[e];
    const __half* B = g_w2h + (size_t)e * HIDDEN * INTER;

    extern __shared__ __align__(16) char smem[];
    uint32_t sbase = smem_u32(smem);

    int tid  = threadIdx.x;
    int lane = tid & 31, warp = tid >> 5;   // 8 warps: 2(m) x 4(n), warp tile 64x32
    int wm = warp & 1, wn = warp >> 1;

    const __half* aptr[2]; int asz[2]; uint32_t coff[2];
    const __half* bptr[2];
#pragma unroll
    for (int p = 0; p < 2; p++) {
        int id  = tid + p * 256;
        int row = id >> 2, ch = id & 3;
        int mg  = m0 + row;
        int rr  = rbase + (mg < cnt ? mg : 0);
        aptr[p] = g_act + (size_t)rr * INTER + ch * 8;
        asz[p]  = (mg < cnt) ? 16 : 0;
        bptr[p] = B + (size_t)(n0 + row) * INTER + ch * 8;
        coff[p] = swz(row, ch);
    }

    auto issue = [&](int kt, int st) {
        uint32_t sA = sbase + st * STG2;
        uint32_t sB = sA + A_ST;
        int k0 = kt * BK;
#pragma unroll
        for (int p = 0; p < 2; p++) {
            cp_async16(sA + coff[p], aptr[p] + k0, asz[p]);
            cp_async16(sB + coff[p], bptr[p] + k0, 16);
        }
        asm volatile("cp.async.commit_group;\n");
    };

    int q  = lane >> 3;
    int qr = (q & 1) * 8 + (lane & 7);
    int cq = q >> 1;
    int rA0 = wm * 64 + qr;
    int rB0 = wn * 32 + qr;
    int swzA = (rA0 >> 1) & 3;
    int swzB = (rB0 >> 1) & 3;
    uint32_t offA[2], offB[2];
#pragma unroll
    for (int kk = 0; kk < 2; kk++) {
        offA[kk] = (uint32_t)(rA0 * 64 + (((2 * kk + cq) ^ swzA) << 4));
        offB[kk] = (uint32_t)(rB0 * 64 + (((2 * kk + cq) ^ swzB) << 4));
    }

    float acc[4][4][4];
#pragma unroll
    for (int i = 0; i < 4; i++)
#pragma unroll
        for (int j = 0; j < 4; j++)
#pragma unroll
            for (int c = 0; c < 4; c++) acc[i][j][c] = 0.f;

    uint32_t a[2][4][4], bf[2][4][2];
    auto ldfrag = [&](uint32_t aS, uint32_t bS, int kk, int buf) {
#pragma unroll
        for (int mt = 0; mt < 4; mt++)
            ldsm4(a[buf][mt], aS + offA[kk] + mt * 1024);
#pragma unroll
        for (int g2 = 0; g2 < 2; g2++) {
            uint32_t r[4];
            ldsm4(r, bS + offB[kk] + g2 * 1024);
            bf[buf][2 * g2][0] = r[0]; bf[buf][2 * g2][1] = r[2];
            bf[buf][2 * g2 + 1][0] = r[1]; bf[buf][2 * g2 + 1][1] = r[3];
        }
    };

    constexpr int KT = INTER / BK;      // 128
    issue(0, 0);
    issue(1, 1);
    int s = 0;
    for (int kt = 0; kt < KT; kt++) {
        if (kt + 1 < KT) {
            asm volatile("cp.async.wait_group 1;\n" ::: "memory");
        } else {
            asm volatile("cp.async.wait_group 0;\n" ::: "memory");
        }
        __syncthreads();
        if (kt + 2 < KT) {
            int s2 = (s >= 1) ? s - 1 : 2;
            issue(kt + 2, s2);
        }
        uint32_t aS = sbase + s * STG2;
        uint32_t bS = aS + A_ST;
        ldfrag(aS, bS, 0, 0);
        ldfrag(aS, bS, 1, 1);
#pragma unroll
        for (int kk = 0; kk < 2; kk++)
#pragma unroll
            for (int mt = 0; mt < 4; mt++)
#pragma unroll
                for (int nt = 0; nt < 4; nt++)
                    mma_f16(acc[mt][nt], a[kk][mt], bf[kk][nt]);
        s = (s == 2) ? 0 : s + 1;
    }

    int lr = lane >> 2, lc = lane & 3;
#pragma unroll
    for (int mt = 0; mt < 4; mt++) {
#pragma unroll
        for (int rh = 0; rh < 2; rh++) {
            int row = wm * 64 + mt * 16 + lr + rh * 8;
            int mg  = m0 + row;
            if (mg >= cnt) continue;
            int gr = rbase + mg;
            int t  = g_row_token[gr];
            float wgt = g_row_weight[gr];
#pragma unroll
            for (int nt = 0; nt < 4; nt++) {
                int col = n0 + wn * 32 + nt * 8 + lc * 2;
                float* op = Out + (size_t)t * HIDDEN + col;
                atomicAdd(op, wgt * acc[mt][nt][2 * rh]);
                atomicAdd(op + 1, wgt * acc[mt][nt][2 * rh + 1]);
            }
        }
    }
}

// ---------------- launch ----------------
extern "C" void kernel_launch(void* const* d_in, const int* in_sizes, int n_in,
                              void* d_out, int out_size) {
    const float* x  = (const float*)d_in[0];
    const float* wg = (const float*)d_in[1];
    const float* w1 = (const float*)d_in[2];
    const float* w3 = (const float*)d_in[3];
    const float* w2 = (const float*)d_in[4];
    float* out = (float*)d_out;

    cudaFuncSetAttribute(k_gemm13, cudaFuncAttributeMaxDynamicSharedMemorySize, SMEM13);
    cudaFuncSetAttribute(k_gemm2,  cudaFuncAttributeMaxDynamicSharedMemorySize, SMEM2);

    const int W4 = NUM_EXPERTS * INTER * HIDDEN / 4;   // 8M float4

    k_setup<<<256, 256>>>(x, wg, out);                 // #1
    k_plan<<<1, 512>>>();                              // #2
    k_cvt<0><<<2048, 256>>>((const float4*)w1, W4);    // #3
    k_cvt<1><<<2048, 256>>>((const float4*)w3, W4);    // #4
    k_cvt<3><<<1024, 256>>>((const float4*)x, NTOK * HIDDEN / 4);  // #5

    dim3 g13(NTOK / BM, INTER / BN, NUM_EXPERTS);      // 16 x 32 x 8
    k_gemm13<<<g13, 256, SMEM13>>>();                  // #6  <- ncu -s 5 lands here

    k_cvt<2><<<2048, 256>>>((const float4*)w2, W4);    // #7
    dim3 g2(NTOK / BM, HIDDEN / BN, NUM_EXPERTS);      // 16 x 8 x 8
    k_gemm2<<<g2, 256, SMEM2>>>(out);                  // #8
}